// round 1
// baseline (speedup 1.0000x reference)
#include <cuda_runtime.h>
#include <cuda_bf16.h>
#include <math.h>

#define SEQ   512
#define BATCH 128
#define DIN   512
#define HDIM  512
#define G3    1536   // 3*HDIM

// ---------------- scratch (device globals: allocation-free) ----------------
__device__ float g_gates[(size_t)SEQ * BATCH * G3];  // precomputed input gates (~402MB)
__device__ float g_Whr[(size_t)DIN * G3];            // W_h rearranged: [k][hh*3 + j]
__device__ float g_h[2][(size_t)BATCH * HDIM];       // ping-pong hidden state
__device__ int   g_reset_mode;                       // 0 = 4-byte words, 2 = bytes

// ---------------- reset dtype sniffing ----------------
// bool may arrive as int32/float32 (4B words holding 0/1 or 0/1.0f) or packed bytes.
__global__ void detect_reset_kernel(const unsigned int* __restrict__ r) {
    if (threadIdx.x == 0 && blockIdx.x == 0) {
        bool word_mode = true;
        for (int i = 0; i < 64; i++) {
            unsigned v = r[i];
            if (!(v == 0u || v == 1u || v == 0x3F800000u)) { word_mode = false; break; }
        }
        g_reset_mode = word_mode ? 0 : 2;
    }
}

// ---------------- rearrange W_h ----------------
// W_h is [DIN, 3H] with gate blocks [z | r | n]. Interleave so that the 3 gate
// columns of hidden unit hh are adjacent: g_Whr[k][hh*3 + j] = W_h[k][j*H + hh].
__global__ void rearrange_wh_kernel(const float* __restrict__ Wh) {
    int idx = blockIdx.x * blockDim.x + threadIdx.x;
    if (idx < DIN * G3) {
        int k  = idx / G3;
        int c  = idx % G3;
        int hh = c / 3;
        int j  = c % 3;
        g_Whr[idx] = Wh[(size_t)k * G3 + j * HDIM + hh];
    }
}

// ---------------- input-gate SGEMM ----------------
// C[M=65536, N=1536] = A[M,512] * B[512,1536] + bias;  A = ins (rows contiguous), B = W_in.
// 128x128 block tile, 8x8 thread tile, BK=8.
__global__ __launch_bounds__(256)
void gates_gemm_kernel(const float* __restrict__ A,
                       const float* __restrict__ B,
                       const float* __restrict__ bias) {
    const int N = G3, K = DIN;
    __shared__ float As[8][128];
    __shared__ float Bs[8][128];

    int bm = blockIdx.y, bn = blockIdx.x;
    int t  = threadIdx.x;
    int tx = t & 15, ty = t >> 4;

    float acc[8][8];
#pragma unroll
    for (int i = 0; i < 8; i++)
#pragma unroll
        for (int j = 0; j < 8; j++) acc[i][j] = 0.f;

    int aRow = t >> 1, aCol = (t & 1) * 4;
    int bRow = t >> 5, bCol = (t & 31) * 4;
    const float* Ab = A + (size_t)bm * 128 * K;
    const float* Bb = B + (size_t)bn * 128;

    for (int k0 = 0; k0 < K; k0 += 8) {
        float4 av = *(const float4*)(Ab + (size_t)aRow * K + k0 + aCol);
        As[aCol + 0][aRow] = av.x;
        As[aCol + 1][aRow] = av.y;
        As[aCol + 2][aRow] = av.z;
        As[aCol + 3][aRow] = av.w;
        float4 bv = *(const float4*)(Bb + (size_t)(k0 + bRow) * N + bCol);
        *(float4*)&Bs[bRow][bCol] = bv;
        __syncthreads();
#pragma unroll
        for (int k = 0; k < 8; k++) {
            float am[8], bm2[8];
            *(float4*)&am[0]  = *(const float4*)&As[k][ty * 8];
            *(float4*)&am[4]  = *(const float4*)&As[k][ty * 8 + 4];
            *(float4*)&bm2[0] = *(const float4*)&Bs[k][tx * 8];
            *(float4*)&bm2[4] = *(const float4*)&Bs[k][tx * 8 + 4];
#pragma unroll
            for (int i = 0; i < 8; i++)
#pragma unroll
                for (int j = 0; j < 8; j++) acc[i][j] += am[i] * bm2[j];
        }
        __syncthreads();
    }

#pragma unroll
    for (int i = 0; i < 8; i++) {
        size_t row = (size_t)bm * 128 + ty * 8 + i;
#pragma unroll
        for (int j = 0; j < 8; j += 4) {
            int col = bn * 128 + tx * 8 + j;
            float4 v;
            v.x = acc[i][j + 0] + bias[col + 0];
            v.y = acc[i][j + 1] + bias[col + 1];
            v.z = acc[i][j + 2] + bias[col + 2];
            v.w = acc[i][j + 3] + bias[col + 3];
            *(float4*)&g_gates[row * N + col] = v;
        }
    }
}

// ---------------- one recurrent step ----------------
// Block tile: 32 batches x 16 hidden units (= 48 interleaved gate columns).
// Grid (4, 32) = 128 blocks. Computes hidden_gates tile, then the full GRU
// update for its (b, hh) tile in-block (interleaved W_h => all 3 gates local).
__global__ __launch_bounds__(256)
void step_kernel(const float* __restrict__ carry,
                 const void*  __restrict__ resets,
                 float* __restrict__ outputs,
                 float* __restrict__ carry_out,
                 int s) {
    __shared__ float Hs[16][33];   // [k][b_local], padded
    __shared__ float Ws[16][48];   // [k][c_local]
    __shared__ float rmask[32];    // 0 if reset else 1

    const float* h_in  = (s == 0) ? carry : g_h[s & 1];
    float*       h_out = g_h[(s + 1) & 1];

    int t  = threadIdx.x;
    int b0 = blockIdx.x * 32;
    int hh0 = blockIdx.y * 16;
    int mode = g_reset_mode;

    if (t < 32) {
        int idx = s * BATCH + (b0 + t);
        bool rs;
        if (mode == 0) rs = ((const int*)resets)[idx] != 0;
        else           rs = ((const unsigned char*)resets)[idx] != 0;
        rmask[t] = rs ? 0.f : 1.f;
    }
    __syncthreads();

    int tx = t & 15, ty = t >> 4;

    // hoist Ws-load index math
    int wk[3], wc[3];
#pragma unroll
    for (int i = 0; i < 3; i++) { int e = t + i * 256; wk[i] = e / 48; wc[i] = e % 48; }

    float acc00 = 0.f, acc01 = 0.f, acc02 = 0.f;
    float acc10 = 0.f, acc11 = 0.f, acc12 = 0.f;

    for (int k0 = 0; k0 < HDIM; k0 += 16) {
        if (t < 128) {
            int b  = t >> 2;
            int kq = (t & 3) * 4;
            float4 hv = *(const float4*)(h_in + (size_t)(b0 + b) * HDIM + k0 + kq);
            float m = rmask[b];
            Hs[kq + 0][b] = hv.x * m;
            Hs[kq + 1][b] = hv.y * m;
            Hs[kq + 2][b] = hv.z * m;
            Hs[kq + 3][b] = hv.w * m;
        }
#pragma unroll
        for (int i = 0; i < 3; i++)
            Ws[wk[i]][wc[i]] = g_Whr[(size_t)(k0 + wk[i]) * G3 + hh0 * 3 + wc[i]];
        __syncthreads();

#pragma unroll
        for (int k = 0; k < 16; k++) {
            float w0 = Ws[k][tx * 3 + 0];
            float w1 = Ws[k][tx * 3 + 1];
            float w2 = Ws[k][tx * 3 + 2];
            float h0 = Hs[k][ty * 2 + 0];
            float h1 = Hs[k][ty * 2 + 1];
            acc00 += h0 * w0; acc01 += h0 * w1; acc02 += h0 * w2;
            acc10 += h1 * w0; acc11 += h1 * w1; acc12 += h1 * w2;
        }
        __syncthreads();
    }

    int hh = hh0 + tx;
#pragma unroll
    for (int i = 0; i < 2; i++) {
        float zh = i ? acc10 : acc00;
        float rh = i ? acc11 : acc01;
        float nh = i ? acc12 : acc02;
        int b = b0 + ty * 2 + i;
        size_t grow = ((size_t)s * BATCH + b) * G3;
        float z_in = g_gates[grow + hh];
        float r_in = g_gates[grow + HDIM + hh];
        float n_in = g_gates[grow + 2 * HDIM + hh];
        float z = 1.f / (1.f + __expf(-(z_in + zh)));
        float r = 1.f / (1.f + __expf(-(r_in + rh)));
        float n = tanhf(n_in + r * nh);
        float hprev = h_in[(size_t)b * HDIM + hh] * rmask[ty * 2 + i];
        float hnew = (1.f - z) * n + z * hprev;
        h_out[(size_t)b * HDIM + hh] = hnew;
        outputs[((size_t)s * BATCH + b) * HDIM + hh] = hnew;
        if (carry_out && s == SEQ - 1) carry_out[(size_t)b * HDIM + hh] = hnew;
    }
}

// ---------------- launcher ----------------
// inputs (metadata order = dict insertion order):
//   0: carry [128,512] f32, 1: ins [512,128,512] f32, 2: resets [512,128] bool,
//   3: W_in [512,1536] f32, 4: b_in [1536] f32, 5: W_h [512,1536] f32
// output: (final_carry, outputs) concatenated: 65536 + 33554432 floats.
extern "C" void kernel_launch(void* const* d_in, const int* in_sizes, int n_in,
                              void* d_out, int out_size) {
    const float* carry = (const float*)d_in[0];
    const float* ins   = (const float*)d_in[1];
    const void*  rsts  = d_in[2];
    const float* W_in  = (const float*)d_in[3];
    const float* b_in  = (const float*)d_in[4];
    const float* W_h   = (const float*)d_in[5];

    float* out = (float*)d_out;
    float* carry_out;
    float* outputs;
    if (out_size == (int)((size_t)SEQ * BATCH * HDIM)) {
        // outputs only (no carry slot)
        carry_out = nullptr;
        outputs   = out;
    } else {
        carry_out = out;
        outputs   = out + (size_t)BATCH * HDIM;
    }

    detect_reset_kernel<<<1, 32>>>((const unsigned int*)rsts);
    rearrange_wh_kernel<<<(DIN * G3 + 255) / 256, 256>>>(W_h);
    gates_gemm_kernel<<<dim3(G3 / 128, (SEQ * BATCH) / 128), 256>>>(ins, W_in, b_in);

    for (int s = 0; s < SEQ; s++) {
        step_kernel<<<dim3(4, 32), 256>>>(carry, rsts, outputs, carry_out, s);
    }
}

// round 2
// speedup vs baseline: 1.2540x; 1.2540x over previous
#include <cuda_runtime.h>
#include <math.h>

#define SEQ   512
#define BATCH 128
#define DIN   512
#define HDIM  512
#define G3    1536
#define NBLK  128

// ---------------- scratch (device globals) ----------------
__device__ float g_gates[(size_t)SEQ * BATCH * G3];   // input gates (~402MB)
__device__ float g_Whr[32][HDIM][48];                 // per hh-group slice: [by][k][c]
__device__ int   g_reset_mode;

// barrier state
__device__ unsigned          g_cnt[8];
__device__ unsigned          g_root;
__device__ volatile unsigned g_gen;

// ---------------- reset dtype sniffing ----------------
__global__ void detect_reset_kernel(const unsigned int* __restrict__ r) {
    if (threadIdx.x == 0 && blockIdx.x == 0) {
        bool word_mode = true;
        for (int i = 0; i < 64; i++) {
            unsigned v = r[i];
            if (!(v == 0u || v == 1u || v == 0x3F800000u)) { word_mode = false; break; }
        }
        g_reset_mode = word_mode ? 0 : 2;
    }
}

// ---------------- rearrange W_h into per-block contiguous slices ----------------
// g_Whr[by][k][c]  where hh = by*16 + c/3, gate j = c%3 ; source W_h[k][j*H + hh]
__global__ void rearrange_wh_kernel(const float* __restrict__ Wh) {
    int idx = blockIdx.x * blockDim.x + threadIdx.x;   // over 32*512*48
    if (idx < 32 * HDIM * 48) {
        int c  = idx % 48;
        int k  = (idx / 48) % HDIM;
        int by = idx / (48 * HDIM);
        int hh = by * 16 + c / 3;
        int j  = c % 3;
        g_Whr[by][k][c] = Wh[(size_t)k * G3 + j * HDIM + hh];
    }
}

// ---------------- input-gate SGEMM (BK=16, double buffered) ----------------
__global__ __launch_bounds__(256)
void gates_gemm_kernel(const float* __restrict__ A,
                       const float* __restrict__ B,
                       const float* __restrict__ bias) {
    const int N = G3, K = DIN;
    __shared__ float As[2][16][128];
    __shared__ float Bs[2][16][128];

    int bm = blockIdx.y, bn = blockIdx.x;
    int t  = threadIdx.x;
    int tx = t & 15, ty = t >> 4;

    float acc[8][8];
#pragma unroll
    for (int i = 0; i < 8; i++)
#pragma unroll
        for (int j = 0; j < 8; j++) acc[i][j] = 0.f;

    // A staging: thread -> row = t>>1, kq = (t&1)*8 ; two float4 (kq, kq+4)
    int aRow = t >> 1, aCol = (t & 1) * 8;
    // B staging: kr = t>>4, col = (t&15)*8 ; two float4
    int bRow = t >> 4, bCol = (t & 15) * 8;
    const float* Ab = A + (size_t)bm * 128 * K;
    const float* Bb = B + (size_t)bn * 128;

    float4 a0, a1, b0, b1;

    // prologue: chunk 0
    a0 = *(const float4*)(Ab + (size_t)aRow * K + aCol);
    a1 = *(const float4*)(Ab + (size_t)aRow * K + aCol + 4);
    b0 = *(const float4*)(Bb + (size_t)bRow * N + bCol);
    b1 = *(const float4*)(Bb + (size_t)bRow * N + bCol + 4);
    {
        float av[8] = {a0.x,a0.y,a0.z,a0.w,a1.x,a1.y,a1.z,a1.w};
#pragma unroll
        for (int i = 0; i < 8; i++) As[0][aCol + i][aRow] = av[i];
        *(float4*)&Bs[0][bRow][bCol]     = b0;
        *(float4*)&Bs[0][bRow][bCol + 4] = b1;
    }
    __syncthreads();

    for (int kc = 0; kc < 32; kc++) {
        int cur = kc & 1;
        if (kc < 31) {
            int k0 = (kc + 1) * 16;
            a0 = *(const float4*)(Ab + (size_t)aRow * K + k0 + aCol);
            a1 = *(const float4*)(Ab + (size_t)aRow * K + k0 + aCol + 4);
            b0 = *(const float4*)(Bb + (size_t)(k0 + bRow) * N + bCol);
            b1 = *(const float4*)(Bb + (size_t)(k0 + bRow) * N + bCol + 4);
        }
#pragma unroll
        for (int k = 0; k < 16; k++) {
            float am[8], bm2[8];
            *(float4*)&am[0]  = *(const float4*)&As[cur][k][ty * 8];
            *(float4*)&am[4]  = *(const float4*)&As[cur][k][ty * 8 + 4];
            *(float4*)&bm2[0] = *(const float4*)&Bs[cur][k][tx * 8];
            *(float4*)&bm2[4] = *(const float4*)&Bs[cur][k][tx * 8 + 4];
#pragma unroll
            for (int i = 0; i < 8; i++)
#pragma unroll
                for (int j = 0; j < 8; j++) acc[i][j] += am[i] * bm2[j];
        }
        if (kc < 31) {
            int nb = cur ^ 1;
            float av[8] = {a0.x,a0.y,a0.z,a0.w,a1.x,a1.y,a1.z,a1.w};
#pragma unroll
            for (int i = 0; i < 8; i++) As[nb][aCol + i][aRow] = av[i];
            *(float4*)&Bs[nb][bRow][bCol]     = b0;
            *(float4*)&Bs[nb][bRow][bCol + 4] = b1;
        }
        __syncthreads();
    }

#pragma unroll
    for (int i = 0; i < 8; i++) {
        size_t row = (size_t)bm * 128 + ty * 8 + i;
#pragma unroll
        for (int j = 0; j < 8; j += 4) {
            int col = bn * 128 + tx * 8 + j;
            float4 v;
            v.x = acc[i][j + 0] + bias[col + 0];
            v.y = acc[i][j + 1] + bias[col + 1];
            v.z = acc[i][j + 2] + bias[col + 2];
            v.w = acc[i][j + 3] + bias[col + 3];
            *(float4*)&g_gates[row * N + col] = v;
        }
    }
}

// ---------------- two-level grid barrier (all 128 blocks resident) ----------------
__device__ __forceinline__ void grid_barrier() {
    __threadfence();
    __syncthreads();
    if (threadIdx.x == 0) {
        unsigned gen = g_gen;
        int grp = blockIdx.x >> 4;            // 8 groups of 16
        if (atomicAdd(&g_cnt[grp], 1u) == 15u) {
            if (atomicAdd(&g_root, 1u) == 7u) {
                g_root = 0;
#pragma unroll
                for (int i = 0; i < 8; i++) g_cnt[i] = 0;
                __threadfence();
                g_gen = gen + 1;
            }
        }
        while (g_gen == gen) { __nanosleep(64); }
    }
    __syncthreads();
    __threadfence();
}

// ---------------- persistent scan kernel ----------------
// 128 blocks (bx=bid&3 -> 32 batches, by=bid>>2 -> 16 hh), 256 threads.
// Thread (tx 0..15, ty 0..15) computes 2 batches x 3 gate-cols (1 hidden unit).
__global__ __launch_bounds__(256)
void scan_kernel(const float* __restrict__ carry,
                 const void*  __restrict__ resets,
                 float* __restrict__ outputs,
                 float* __restrict__ carry_out) {
    __shared__ float Ws[2][32][48];
    __shared__ float Hs[2][32][33];
    __shared__ float rmask_s[32];

    int t   = threadIdx.x;
    int bid = blockIdx.x;
    int bx  = bid & 3, by = bid >> 2;
    int b0  = bx * 32, hh0 = by * 16;
    int tx  = t & 15,  ty = t >> 4;
    int mode = g_reset_mode;

    // staging index precompute
    int hb  = t >> 3;            // batch 0..31 for H staging
    int hkq = (t & 7) * 4;       // k offset 0..28
    const float* Wslice = &g_Whr[by][0][0];   // 512*48 contiguous floats

    int hh = hh0 + tx;

    for (int s = 0; s < SEQ; s++) {
        const float* h_in = (s == 0) ? carry
                                     : outputs + (size_t)(s - 1) * BATCH * HDIM;
        if (t < 32) {
            int idx = s * BATCH + b0 + t;
            bool rs = (mode == 0) ? (((const int*)resets)[idx] != 0)
                                  : (((const unsigned char*)resets)[idx] != 0);
            rmask_s[t] = rs ? 0.f : 1.f;
        }
        // prefetch gates + hprev for epilogue
        int bA = b0 + ty * 2, bB = bA + 1;
        size_t gA = ((size_t)s * BATCH + bA) * G3;
        size_t gB = ((size_t)s * BATCH + bB) * G3;
        float zA = g_gates[gA + hh], rA = g_gates[gA + HDIM + hh], nA = g_gates[gA + 2*HDIM + hh];
        float zB = g_gates[gB + hh], rB = g_gates[gB + HDIM + hh], nB = g_gates[gB + 2*HDIM + hh];
        float hpA = h_in[(size_t)bA * HDIM + hh];
        float hpB = h_in[(size_t)bB * HDIM + hh];

        __syncthreads();   // rmask ready; previous step's smem use complete (barrier)

        // stage chunk 0
        {
            float4 hv = *(const float4*)(h_in + (size_t)(b0 + hb) * HDIM + hkq);
            float m = rmask_s[hb];
            Hs[0][hkq + 0][hb] = hv.x * m;
            Hs[0][hkq + 1][hb] = hv.y * m;
            Hs[0][hkq + 2][hb] = hv.z * m;
            Hs[0][hkq + 3][hb] = hv.w * m;
            float4 wv0 = *(const float4*)(Wslice + t * 4);
            *(float4*)((float*)&Ws[0][0][0] + t * 4) = wv0;
            if (t < 128) {
                float4 wv1 = *(const float4*)(Wslice + (t + 256) * 4);
                *(float4*)((float*)&Ws[0][0][0] + (t + 256) * 4) = wv1;
            }
        }
        __syncthreads();

        float acc00 = 0.f, acc01 = 0.f, acc02 = 0.f;
        float acc10 = 0.f, acc11 = 0.f, acc12 = 0.f;

        for (int kc = 0; kc < 16; kc++) {
            int cur = kc & 1;
            float4 hv, wv0, wv1;
            if (kc < 15) {
                int k0 = (kc + 1) * 32;
                hv  = *(const float4*)(h_in + (size_t)(b0 + hb) * HDIM + k0 + hkq);
                wv0 = *(const float4*)(Wslice + k0 * 48 + t * 4);
                if (t < 128)
                    wv1 = *(const float4*)(Wslice + k0 * 48 + (t + 256) * 4);
            }
#pragma unroll
            for (int k = 0; k < 32; k++) {
                float w0 = Ws[cur][k][tx * 3 + 0];
                float w1 = Ws[cur][k][tx * 3 + 1];
                float w2 = Ws[cur][k][tx * 3 + 2];
                float h0 = Hs[cur][k][ty * 2 + 0];
                float h1 = Hs[cur][k][ty * 2 + 1];
                acc00 += h0 * w0; acc01 += h0 * w1; acc02 += h0 * w2;
                acc10 += h1 * w0; acc11 += h1 * w1; acc12 += h1 * w2;
            }
            if (kc < 15) {
                int nb = cur ^ 1;
                float m = rmask_s[hb];
                Hs[nb][hkq + 0][hb] = hv.x * m;
                Hs[nb][hkq + 1][hb] = hv.y * m;
                Hs[nb][hkq + 2][hb] = hv.z * m;
                Hs[nb][hkq + 3][hb] = hv.w * m;
                *(float4*)((float*)&Ws[nb][0][0] + t * 4) = wv0;
                if (t < 128)
                    *(float4*)((float*)&Ws[nb][0][0] + (t + 256) * 4) = wv1;
            }
            __syncthreads();
        }

        // epilogue: GRU update for (bA, hh) and (bB, hh)
        float mA = rmask_s[ty * 2 + 0];
        float mB = rmask_s[ty * 2 + 1];
        {
            float z = 1.f / (1.f + __expf(-(zA + acc00)));
            float r = 1.f / (1.f + __expf(-(rA + acc01)));
            float n = tanhf(nA + r * acc02);
            float hnew = (1.f - z) * n + z * (hpA * mA);
            outputs[((size_t)s * BATCH + bA) * HDIM + hh] = hnew;
            if (carry_out && s == SEQ - 1) carry_out[(size_t)bA * HDIM + hh] = hnew;
        }
        {
            float z = 1.f / (1.f + __expf(-(zB + acc10)));
            float r = 1.f / (1.f + __expf(-(rB + acc11)));
            float n = tanhf(nB + r * acc12);
            float hnew = (1.f - z) * n + z * (hpB * mB);
            outputs[((size_t)s * BATCH + bB) * HDIM + hh] = hnew;
            if (carry_out && s == SEQ - 1) carry_out[(size_t)bB * HDIM + hh] = hnew;
        }

        grid_barrier();
    }
}

// ---------------- launcher ----------------
extern "C" void kernel_launch(void* const* d_in, const int* in_sizes, int n_in,
                              void* d_out, int out_size) {
    const float* carry = (const float*)d_in[0];
    const float* ins   = (const float*)d_in[1];
    const void*  rsts  = d_in[2];
    const float* W_in  = (const float*)d_in[3];
    const float* b_in  = (const float*)d_in[4];
    const float* W_h   = (const float*)d_in[5];

    float* out = (float*)d_out;
    float* carry_out;
    float* outputs;
    if (out_size == (int)((size_t)SEQ * BATCH * HDIM)) {
        carry_out = nullptr;
        outputs   = out;
    } else {
        carry_out = out;
        outputs   = out + (size_t)BATCH * HDIM;
    }

    detect_reset_kernel<<<1, 32>>>((const unsigned int*)rsts);
    rearrange_wh_kernel<<<(32 * HDIM * 48 + 255) / 256, 256>>>(W_h);
    gates_gemm_kernel<<<dim3(G3 / 128, (SEQ * BATCH) / 128), 256>>>(ins, W_in, b_in);
    scan_kernel<<<NBLK, 256>>>(carry, rsts, outputs, carry_out);
}

// round 4
// speedup vs baseline: 1.6807x; 1.3402x over previous
#include <cuda_runtime.h>
#include <math.h>

#define SEQ   512
#define BATCH 128
#define DIN   512
#define HDIM  512
#define G3    1536
#define SCAN_BLOCKS 128

// ---------------- scratch (device globals) ----------------
__device__ float g_gates[(size_t)SEQ * BATCH * G3];      // input gates (~402MB)
// W_h rearranged, k-pair interleaved per 16-hh block:
// g_Whr[by][k2][c][p]  (by 0..31, k2 0..255, c = hh_local*3+gate, p = k parity)
__device__ float g_Whr[32][256][48][2];
__device__ int   g_reset_mode;

// barrier state
__device__ unsigned          g_cnt[8];
__device__ unsigned          g_root;
__device__ volatile unsigned g_gen;

// ---------------- packed fp32x2 FMA (sm_103a) ----------------
__device__ __forceinline__ float2 ffma2(float2 a, float2 b, float2 c) {
    float2 d;
    asm("fma.rn.f32x2 %0, %1, %2, %3;"
        : "=l"(*(unsigned long long*)&d)
        : "l"(*(unsigned long long*)&a),
          "l"(*(unsigned long long*)&b),
          "l"(*(unsigned long long*)&c));
    return d;
}

// ---------------- init + reset dtype sniffing ----------------
__global__ void init_kernel(const unsigned int* __restrict__ r) {
    if (threadIdx.x == 0 && blockIdx.x == 0) {
        bool word_mode = true;
        for (int i = 0; i < 64; i++) {
            unsigned v = r[i];
            if (!(v == 0u || v == 1u || v == 0x3F800000u)) { word_mode = false; break; }
        }
        g_reset_mode = word_mode ? 0 : 2;
        g_root = 0;
#pragma unroll
        for (int i = 0; i < 8; i++) g_cnt[i] = 0;
    }
}

// ---------------- rearrange W_h ----------------
// g_Whr[by][k2][c][p] = Wh[2*k2+p][ (c%3)*512 + by*16 + c/3 ]
__global__ void rearrange_wh_kernel(const float* __restrict__ Wh) {
    int idx = blockIdx.x * blockDim.x + threadIdx.x;   // over 32*256*48*2
    if (idx < 32 * 256 * 48 * 2) {
        int p  = idx & 1;
        int c  = (idx >> 1) % 48;
        int k2 = ((idx >> 1) / 48) & 255;
        int by = idx / (2 * 48 * 256);
        int k  = 2 * k2 + p;
        int hh = by * 16 + c / 3;
        int j  = c % 3;
        ((float*)g_Whr)[idx] = Wh[(size_t)k * G3 + j * HDIM + hh];
    }
}

// ---------------- input-gate SGEMM, f32x2 k-pair, 128x64 tile ----------------
// grid (24, 512): cols [bx*64, +64), rows [by*128, +128). Thread: 8 rows x 4 cols.
// Cols per thread: tx + 16*j  (conflict-free Bs reads).
#define AS(buf,k2,row) As[((buf)*8 + (k2)) * 130 + (row)]
#define BS(buf,k2,n)   Bs[((buf)*8 + (k2)) * 65  + (n)]
__global__ __launch_bounds__(256)
void gates_gemm_kernel(const float* __restrict__ A,
                       const float* __restrict__ B,
                       const float* __restrict__ bias) {
    __shared__ float2 As[2 * 8 * 130];   // [buf][k2][row] = {a(2k),a(2k+1)}
    __shared__ float2 Bs[2 * 8 * 65];    // [buf][k2][n]   = {b(2k),b(2k+1)}

    const int N = G3, K = DIN;
    int bn = blockIdx.x, bm = blockIdx.y;
    int t  = threadIdx.x;
    int tx = t & 15, ty = t >> 4;

    float2 acc[8][4];
#pragma unroll
    for (int i = 0; i < 8; i++)
#pragma unroll
        for (int j = 0; j < 4; j++) acc[i][j] = make_float2(0.f, 0.f);

    // A staging map: slot t -> (row t&127, kq (t>>7)*4); slot t+256 -> kq+8
    int ar  = t & 127;
    int akq = (t >> 7) * 4;
    // B staging map: n = t&63, kslot = t>>6 (4 consecutive k)
    int bnl = t & 63;
    int bks = (t >> 6) * 4;

    const float* Ab = A + (size_t)bm * 128 * K;
    const float* Bb = B + (size_t)bn * 64;

    float4 a0, a1;
    float  bv[4];

    // prologue chunk 0
    a0 = *(const float4*)(Ab + (size_t)ar * K + akq);
    a1 = *(const float4*)(Ab + (size_t)ar * K + akq + 8);
#pragma unroll
    for (int i = 0; i < 4; i++) bv[i] = Bb[(size_t)(bks + i) * N + bnl];
    AS(0, (akq >> 1),     ar) = make_float2(a0.x, a0.y);
    AS(0, (akq >> 1) + 1, ar) = make_float2(a0.z, a0.w);
    AS(0, (akq >> 1) + 4, ar) = make_float2(a1.x, a1.y);
    AS(0, (akq >> 1) + 5, ar) = make_float2(a1.z, a1.w);
    BS(0, (bks >> 1),     bnl) = make_float2(bv[0], bv[1]);
    BS(0, (bks >> 1) + 1, bnl) = make_float2(bv[2], bv[3]);
    __syncthreads();

    for (int kc = 0; kc < 32; kc++) {
        int cur = kc & 1;
        if (kc < 31) {
            int k0 = (kc + 1) * 16;
            a0 = *(const float4*)(Ab + (size_t)ar * K + k0 + akq);
            a1 = *(const float4*)(Ab + (size_t)ar * K + k0 + akq + 8);
#pragma unroll
            for (int i = 0; i < 4; i++) bv[i] = Bb[(size_t)(k0 + bks + i) * N + bnl];
        }
#pragma unroll
        for (int k2 = 0; k2 < 8; k2++) {
            float2 areg[8], breg[4];
#pragma unroll
            for (int i = 0; i < 8; i++) areg[i] = AS(cur, k2, ty * 8 + i);
#pragma unroll
            for (int j = 0; j < 4; j++) breg[j] = BS(cur, k2, tx + 16 * j);
#pragma unroll
            for (int i = 0; i < 8; i++)
#pragma unroll
                for (int j = 0; j < 4; j++)
                    acc[i][j] = ffma2(areg[i], breg[j], acc[i][j]);
        }
        if (kc < 31) {
            int nb = cur ^ 1;
            AS(nb, (akq >> 1),     ar) = make_float2(a0.x, a0.y);
            AS(nb, (akq >> 1) + 1, ar) = make_float2(a0.z, a0.w);
            AS(nb, (akq >> 1) + 4, ar) = make_float2(a1.x, a1.y);
            AS(nb, (akq >> 1) + 5, ar) = make_float2(a1.z, a1.w);
            BS(nb, (bks >> 1),     bnl) = make_float2(bv[0], bv[1]);
            BS(nb, (bks >> 1) + 1, bnl) = make_float2(bv[2], bv[3]);
        }
        __syncthreads();
    }

    float bsv[4];
#pragma unroll
    for (int j = 0; j < 4; j++) bsv[j] = bias[bn * 64 + tx + 16 * j];
#pragma unroll
    for (int i = 0; i < 8; i++) {
        size_t row = (size_t)bm * 128 + ty * 8 + i;
#pragma unroll
        for (int j = 0; j < 4; j++) {
            int col = bn * 64 + tx + 16 * j;
            g_gates[row * N + col] = acc[i][j].x + acc[i][j].y + bsv[j];
        }
    }
}

// ---------------- two-level grid barrier (128 blocks) ----------------
__device__ __forceinline__ void grid_barrier() {
    __threadfence();
    __syncthreads();
    if (threadIdx.x == 0) {
        unsigned gen = g_gen;
        int grp = blockIdx.x >> 4;
        if (atomicAdd(&g_cnt[grp], 1u) == 15u) {
            if (atomicAdd(&g_root, 1u) == 7u) {
                g_root = 0;
#pragma unroll
                for (int i = 0; i < 8; i++) g_cnt[i] = 0;
                __threadfence();
                g_gen = gen + 1;
            }
        }
        while (g_gen == gen) { __nanosleep(64); }
    }
    __syncthreads();
    __threadfence();
}

// ---------------- persistent scan kernel ----------------
// 128 blocks (bx=bid&3 -> 32 batches, by=bid>>2 -> 16 hh), 256 threads.
// W_h slice (96KB) persistent in smem, k-pair layout. H staged per 64-k chunk
// as {h(2k),h(2k+1)} float2. Accumulators are f32x2 over k-parity.
__global__ __launch_bounds__(256)
void scan_kernel(const float* __restrict__ carry,
                 const void*  __restrict__ resets,
                 float* __restrict__ outputs,
                 float* __restrict__ carry_out) {
    extern __shared__ float sm[];
    float*  Wp    = sm;                              // 24576 floats ([k2][48] float2)
    float2* Hbuf  = (float2*)(sm + 24576);           // [2][32][33] float2
    float*  rmask = sm + 24576 + 2 * 32 * 33 * 2;    // 32 floats

    int t   = threadIdx.x;
    int bid = blockIdx.x;
    int bx  = bid & 3, by = bid >> 2;
    int b0  = bx * 32, hh0 = by * 16;
    int tx  = t & 15,  ty = t >> 4;
    int mode = g_reset_mode;
    int hh  = hh0 + tx;

    // one-time: W slice into smem (coalesced)
    {
        const float* Wslice = (const float*)g_Whr[by];
        for (int i = t * 4; i < 24576; i += 256 * 4)
            *(float4*)(Wp + i) = *(const float4*)(Wslice + i);
    }

    int hb = t >> 3;          // batch 0..31 for H staging
    int hk = (t & 7) * 8;     // k offset within 64-chunk

    const float2* Wp2 = (const float2*)Wp;

    for (int s = 0; s < SEQ; s++) {
        const float* h_in = (s == 0) ? carry
                                     : outputs + (size_t)(s - 1) * BATCH * HDIM;
        if (t < 32) {
            int idx = s * BATCH + b0 + t;
            bool rs = (mode == 0) ? (((const int*)resets)[idx] != 0)
                                  : (((const unsigned char*)resets)[idx] != 0);
            rmask[t] = rs ? 0.f : 1.f;
        }

        // prefetch epilogue operands
        int bA = b0 + ty * 2, bB = bA + 1;
        size_t gA = ((size_t)s * BATCH + bA) * G3;
        size_t gB = ((size_t)s * BATCH + bB) * G3;
        float zA = g_gates[gA + hh], rA = g_gates[gA + HDIM + hh], nA = g_gates[gA + 2*HDIM + hh];
        float zB = g_gates[gB + hh], rB = g_gates[gB + HDIM + hh], nB = g_gates[gB + 2*HDIM + hh];
        float hpA = h_in[(size_t)bA * HDIM + hh];
        float hpB = h_in[(size_t)bB * HDIM + hh];

        __syncthreads();   // rmask ready; prev-step smem use complete

        // stage chunk 0 (k 0..63) as k-pairs
        {
            float m = rmask[hb];
            const float* hp = h_in + (size_t)(b0 + hb) * HDIM + hk;
            float4 v0 = *(const float4*)(hp);
            float4 v1 = *(const float4*)(hp + 4);
            int k2b = hk >> 1;
            Hbuf[(k2b + 0) * 33 + hb] = make_float2(v0.x * m, v0.y * m);
            Hbuf[(k2b + 1) * 33 + hb] = make_float2(v0.z * m, v0.w * m);
            Hbuf[(k2b + 2) * 33 + hb] = make_float2(v1.x * m, v1.y * m);
            Hbuf[(k2b + 3) * 33 + hb] = make_float2(v1.z * m, v1.w * m);
        }
        __syncthreads();

        float2 acc00 = make_float2(0.f,0.f), acc01 = acc00, acc02 = acc00;
        float2 acc10 = acc00, acc11 = acc00, acc12 = acc00;

        for (int kc = 0; kc < 8; kc++) {
            int cur = kc & 1;
            float4 v0, v1;
            if (kc < 7) {
                const float* hp = h_in + (size_t)(b0 + hb) * HDIM + (kc + 1) * 64 + hk;
                v0 = *(const float4*)(hp);
                v1 = *(const float4*)(hp + 4);
            }
            const float2* Hc = Hbuf + cur * (32 * 33);
            const float2* Wk = Wp2 + (size_t)(kc * 32) * 48 + tx * 3;
#pragma unroll
            for (int k2 = 0; k2 < 32; k2++) {
                float2 w0 = Wk[k2 * 48 + 0];
                float2 w1 = Wk[k2 * 48 + 1];
                float2 w2 = Wk[k2 * 48 + 2];
                float2 hA = Hc[k2 * 33 + ty * 2];
                float2 hB = Hc[k2 * 33 + ty * 2 + 1];
                acc00 = ffma2(hA, w0, acc00);
                acc01 = ffma2(hA, w1, acc01);
                acc02 = ffma2(hA, w2, acc02);
                acc10 = ffma2(hB, w0, acc10);
                acc11 = ffma2(hB, w1, acc11);
                acc12 = ffma2(hB, w2, acc12);
            }
            if (kc < 7) {
                float2* Hn = Hbuf + (cur ^ 1) * (32 * 33);
                float m = rmask[hb];
                int k2b = hk >> 1;
                Hn[(k2b + 0) * 33 + hb] = make_float2(v0.x * m, v0.y * m);
                Hn[(k2b + 1) * 33 + hb] = make_float2(v0.z * m, v0.w * m);
                Hn[(k2b + 2) * 33 + hb] = make_float2(v1.x * m, v1.y * m);
                Hn[(k2b + 3) * 33 + hb] = make_float2(v1.z * m, v1.w * m);
            }
            __syncthreads();
        }

        // epilogue
        float mA = rmask[ty * 2 + 0];
        float mB = rmask[ty * 2 + 1];
        {
            float zh = acc00.x + acc00.y, rh = acc01.x + acc01.y, nh = acc02.x + acc02.y;
            float z = 1.f / (1.f + __expf(-(zA + zh)));
            float r = 1.f / (1.f + __expf(-(rA + rh)));
            float n = tanhf(nA + r * nh);
            float hnew = (1.f - z) * n + z * (hpA * mA);
            outputs[((size_t)s * BATCH + bA) * HDIM + hh] = hnew;
            if (carry_out && s == SEQ - 1) carry_out[(size_t)bA * HDIM + hh] = hnew;
        }
        {
            float zh = acc10.x + acc10.y, rh = acc11.x + acc11.y, nh = acc12.x + acc12.y;
            float z = 1.f / (1.f + __expf(-(zB + zh)));
            float r = 1.f / (1.f + __expf(-(rB + rh)));
            float n = tanhf(nB + r * nh);
            float hnew = (1.f - z) * n + z * (hpB * mB);
            outputs[((size_t)s * BATCH + bB) * HDIM + hh] = hnew;
            if (carry_out && s == SEQ - 1) carry_out[(size_t)bB * HDIM + hh] = hnew;
        }

        if (s < SEQ - 1) grid_barrier();
    }
}

// ---------------- launcher (single stream, sequential) ----------------
extern "C" void kernel_launch(void* const* d_in, const int* in_sizes, int n_in,
                              void* d_out, int out_size) {
    const float* carry = (const float*)d_in[0];
    const float* ins   = (const float*)d_in[1];
    const void*  rsts  = d_in[2];
    const float* W_in  = (const float*)d_in[3];
    const float* b_in  = (const float*)d_in[4];
    const float* W_h   = (const float*)d_in[5];

    float* out = (float*)d_out;
    float* carry_out;
    float* outputs;
    if (out_size == (int)((size_t)SEQ * BATCH * HDIM)) {
        carry_out = nullptr;
        outputs   = out;
    } else {
        carry_out = out;
        outputs   = out + (size_t)BATCH * HDIM;
    }

    const int SMEM_SCAN = (24576 + 2 * 32 * 33 * 2 + 32) * sizeof(float);
    cudaFuncSetAttribute(scan_kernel,
                         cudaFuncAttributeMaxDynamicSharedMemorySize, SMEM_SCAN);

    init_kernel<<<1, 32>>>((const unsigned int*)rsts);
    rearrange_wh_kernel<<<(32 * 256 * 48 * 2 + 255) / 256, 256>>>(W_h);
    gates_gemm_kernel<<<dim3(G3 / 64, (SEQ * BATCH) / 128), 256>>>(ins, W_in, b_in);
    scan_kernel<<<SCAN_BLOCKS, 256, SMEM_SCAN>>>(carry, rsts, outputs, carry_out);
}